// round 3
// baseline (speedup 1.0000x reference)
#include <cuda_runtime.h>
#include <cuda_fp16.h>

#define NC 32
#define NLEV 6
#define TOTAL 349440   // sum of res^2 over 6 levels

// Pool: [face][texel(level-major)][channel], HALF, 134 MB
__device__ __half POOLH[6ll * TOTAL * NC];
// Scratch: unfiltered pooled levels 1..5, channel-last HALF. 33.5 MB
__device__ __half SCRATCH[523776ll * NC];

__constant__ int d_offs[NLEV] = {0, 262144, 327680, 344064, 348160, 349184};

// Fused-filter per-level tables (levels 1..5), 16x16 tiles
__constant__ int   F_start[5]  = {0, 1536, 1920, 2016, 2040};   // total 2046 blocks
__constant__ int   F_inOff[5]  = {0, 393216, 491520, 516096, 522240};
__constant__ int   F_poolOff[5]= {262144, 327680, 344064, 348160, 349184};
__constant__ float F_a2[5]     = {0.00243101246f, 0.030233088f, 0.137822329f, 0.419904f, 0.96059601f}; // rough^4

// ---------------------------------------------------------------------------
// K1: transpose feature (C,6,512,512) -> pool level0 (half, channel-last)
//     AND compute level-1 avg-pool into SCRATCH (half)
// ---------------------------------------------------------------------------
__global__ void k_transpose_pool1(const float* __restrict__ feat) {
    int f = blockIdx.z;
    int x0 = blockIdx.x * 64;
    int y0 = blockIdx.y * 2;
    __shared__ float s[32 * 129];
    int tid = threadIdx.x;

    for (int i = tid; i < 32 * 32; i += 256) {
        int c = i >> 5, v = i & 31;
        int t0 = v * 4;
        int yy = y0 + (t0 >> 6), xx = x0 + (t0 & 63);
        float4 d = *(const float4*)&feat[(((size_t)c * 6 + f) * 512 + yy) * 512 + xx];
        s[c * 129 + t0 + 0] = d.x;
        s[c * 129 + t0 + 1] = d.y;
        s[c * 129 + t0 + 2] = d.z;
        s[c * 129 + t0 + 3] = d.w;
    }
    __syncthreads();

    uint4* P4 = (uint4*)POOLH;   // one uint4 = 8 half channels
    for (int i = tid; i < 512; i += 256) {
        int t = i >> 2, q = i & 3;
        int yy = y0 + (t >> 6), xx = x0 + (t & 63);
        const float* sp = &s[(8 * q) * 129 + t];
        __half2 h0 = __floats2half2_rn(sp[0],       sp[129]);
        __half2 h1 = __floats2half2_rn(sp[2 * 129], sp[3 * 129]);
        __half2 h2 = __floats2half2_rn(sp[4 * 129], sp[5 * 129]);
        __half2 h3 = __floats2half2_rn(sp[6 * 129], sp[7 * 129]);
        uint4 o;
        o.x = *(unsigned*)&h0; o.y = *(unsigned*)&h1;
        o.z = *(unsigned*)&h2; o.w = *(unsigned*)&h3;
        P4[((size_t)f * TOTAL + (size_t)yy * 512 + xx) * 4 + q] = o;
    }
    // level-1 pool (half scratch)
    for (int i = tid; i < 1024; i += 256) {
        int c = i & 31, to = i >> 5;
        int t00 = 2 * to, t10 = 64 + 2 * to;
        float v = 0.25f * (s[c * 129 + t00] + s[c * 129 + t00 + 1] +
                           s[c * 129 + t10] + s[c * 129 + t10 + 1]);
        SCRATCH[(((size_t)f * 65536 + (size_t)(y0 >> 1) * 256 + (x0 >> 1) + to) * 32) + c] =
            __float2half_rn(v);
    }
}

// ---------------------------------------------------------------------------
// Pool pair: two levels computed directly from one source level (kxk avg).
// Item = (texel, q-slot of 8 half channels).
// ---------------------------------------------------------------------------
__global__ void k_pool_pair(int split, int total,
                            int Ra, int ka, size_t dstA,
                            int Rb, int kb, size_t dstB,
                            size_t srcOff, int Rin) {
    int idx = blockIdx.x * 256 + threadIdx.x;
    if (idx >= total) return;
    int Rout, k; size_t dst; int rel;
    if (idx < split) { Rout = Ra; k = ka; dst = dstA; rel = idx; }
    else             { Rout = Rb; k = kb; dst = dstB; rel = idx - split; }
    int q = rel & 3;
    int t = rel >> 2;
    int f = t / (Rout * Rout);
    int rem = t - f * Rout * Rout;
    int oy = rem / Rout, ox = rem % Rout;
    const uint4* S4 = (const uint4*)SCRATCH;
    size_t sb = (srcOff + ((size_t)f * Rin + oy * k) * Rin + ox * k) * 4 + q;
    float a[8];
#pragma unroll
    for (int i = 0; i < 8; i++) a[i] = 0.f;
    for (int dy = 0; dy < k; dy++)
        for (int dx = 0; dx < k; dx++) {
            uint4 hv = S4[sb + ((size_t)dy * Rin + dx) * 4];
            const unsigned* p = &hv.x;
#pragma unroll
            for (int j = 0; j < 4; j++) {
                float2 fv = __half22float2(*(const __half2*)&p[j]);
                a[2 * j] += fv.x; a[2 * j + 1] += fv.y;
            }
        }
    float sc = 1.f / (float)(k * k);
    __half2 h0 = __floats2half2_rn(a[0] * sc, a[1] * sc);
    __half2 h1 = __floats2half2_rn(a[2] * sc, a[3] * sc);
    __half2 h2 = __floats2half2_rn(a[4] * sc, a[5] * sc);
    __half2 h3 = __floats2half2_rn(a[6] * sc, a[7] * sc);
    uint4 o;
    o.x = *(unsigned*)&h0; o.y = *(unsigned*)&h1;
    o.z = *(unsigned*)&h2; o.w = *(unsigned*)&h3;
    ((uint4*)SCRATCH)[(dst + (size_t)t) * 4 + q] = o;
}

// ---------------------------------------------------------------------------
// Fused GGX filter, all levels, 16x16 tiles (20x20 halo, fp16 smem).
// One thread = one texel (all 32 channels in registers, weights in registers).
// ---------------------------------------------------------------------------
__global__ void __launch_bounds__(256) k_filter_all() {
    int bid = blockIdx.x;
    int li = 0;
#pragma unroll
    for (int k = 1; k < 5; k++) if (bid >= F_start[k]) li = k;
    int R = 256 >> li;
    int nb = R >> 4;
    int rel = bid - F_start[li];
    int f  = rel / (nb * nb);
    int r2 = rel - f * nb * nb;
    int y0 = (r2 / nb) * 16, x0 = (r2 % nb) * 16;
    size_t inOff   = (size_t)F_inOff[li];
    size_t poolOff = (size_t)F_poolOff[li];
    float a2 = F_a2[li];

    __shared__ uint4 hs[20 * 20 * 4];   // 25.6 KB
    int tid = threadIdx.x;
    const uint4* S4 = (const uint4*)SCRATCH;

    for (int i = tid; i < 1600; i += 256) {
        int t = i >> 2, q = i & 3;
        int hy = t / 20, hx = t - hy * 20;
        int gy = min(max(y0 - 2 + hy, 0), R - 1);
        int gx = min(max(x0 - 2 + hx, 0), R - 1);
        hs[i] = S4[(inOff + ((size_t)f * R + gy) * R + gx) * 4 + q];
    }
    __syncthreads();

    int ty = tid >> 4, tx = tid & 15;
    int gy = y0 + ty, gx = x0 + tx;
    float invR2 = 2.0f / (float)R;
    float u = (gx + 0.5f) * invR2 - 1.f;
    float v = (gy + 0.5f) * invR2 - 1.f;
    float rn0 = rsqrtf(1.f + u * u + v * v);

    float w25[25];
    float wsum = 0.f;
#pragma unroll
    for (int n = 0; n < 25; n++) {
        int di = n / 5 - 2, dj = n % 5 - 2;
        int iy = min(max(gy + di, 0), R - 1);
        int jx = min(max(gx + dj, 0), R - 1);
        float vv = (iy + 0.5f) * invR2 - 1.f;
        float uu = (jx + 0.5f) * invR2 - 1.f;
        float cs = (1.f + u * uu + v * vv) * rn0 * rsqrtf(1.f + uu * uu + vv * vv);
        cs = fminf(cs, 1.f);
        float wg = 0.f;
        if (cs > 0.f) {
            float dn = cs * cs * (a2 - 1.f) + 1.f;
            wg = a2 / (3.14159265358979f * dn * dn);
        }
        w25[n] = wg;
        wsum += wg;
    }
    float ws = 1.f / fmaxf(wsum, 1e-8f);

    float acc[32];
#pragma unroll
    for (int i = 0; i < 32; i++) acc[i] = 0.f;
#pragma unroll
    for (int n = 0; n < 25; n++) {
        float wg = w25[n];
        int hy = ty + n / 5, hx = tx + n % 5;
        const uint4* hp = &hs[(hy * 20 + hx) * 4];
#pragma unroll
        for (int k2 = 0; k2 < 4; k2++) {
            uint4 hv = hp[k2];
            const unsigned* p = &hv.x;
#pragma unroll
            for (int j = 0; j < 4; j++) {
                float2 fv = __half22float2(*(const __half2*)&p[j]);
                acc[k2 * 8 + 2 * j]     += wg * fv.x;
                acc[k2 * 8 + 2 * j + 1] += wg * fv.y;
            }
        }
    }

    uint4* P4 = (uint4*)POOLH;
    size_t ob = ((size_t)f * TOTAL + poolOff + (size_t)gy * R + gx) * 4;
#pragma unroll
    for (int k2 = 0; k2 < 4; k2++) {
        __half2 h0 = __floats2half2_rn(acc[k2 * 8 + 0] * ws, acc[k2 * 8 + 1] * ws);
        __half2 h1 = __floats2half2_rn(acc[k2 * 8 + 2] * ws, acc[k2 * 8 + 3] * ws);
        __half2 h2 = __floats2half2_rn(acc[k2 * 8 + 4] * ws, acc[k2 * 8 + 5] * ws);
        __half2 h3 = __floats2half2_rn(acc[k2 * 8 + 6] * ws, acc[k2 * 8 + 7] * ws);
        uint4 o;
        o.x = *(unsigned*)&h0; o.y = *(unsigned*)&h1;
        o.z = *(unsigned*)&h2; o.w = *(unsigned*)&h3;
        P4[ob + k2] = o;
    }
}

// ---------------------------------------------------------------------------
// Fetch: 4 lanes per query, one uint4 (8 half channels) per lane per tap.
// ---------------------------------------------------------------------------
__global__ void k_fetch(const float* __restrict__ w, const float* __restrict__ rr,
                        float* __restrict__ out, int B) {
    long g = (long)blockIdx.x * 256 + threadIdx.x;
    if (g >= (long)B * 4) return;
    int b = (int)(g >> 2), q = (int)(g & 3);

    float dx = w[b * 3 + 0] * 2.f - 1.f;
    float dy = w[b * 3 + 1] * 2.f - 1.f;
    float dz = w[b * 3 + 2] * 2.f - 1.f;
    float ax = fabsf(dx), ay = fabsf(dy), az = fabsf(dz);
    bool cx = (ax >= ay) && (ax >= az);
    bool cy = (ay >= az) && !cx;
    float ma = cx ? ax : (cy ? ay : az);
    int face = cx ? (dx > 0.f ? 0 : 1) : (cy ? (dy > 0.f ? 2 : 3) : (dz > 0.f ? 4 : 5));
    float un = cx ? (dx > 0.f ? -dz : dz) : (cy ? dx : (dz > 0.f ? dx : -dx));
    float vn = cx ? -dy : (cy ? (dy > 0.f ? dz : -dz) : -dy);
    float inv = 1.f / ma;
    float u01 = (un * inv + 1.f) * 0.5f;
    float v01 = (vn * inv + 1.f) * 0.5f;

    float lev = fminf(fmaxf((rr[b] - 0.03f) * (1.f / 0.96f), 0.f), 1.f) * 5.f;
    int l0 = (int)lev;
    if (l0 > 5) l0 = 5;
    float t = lev - (float)l0;
    int l1 = min(l0 + 1, 5);

    const uint4* P4 = (const uint4*)POOLH;
    size_t fb = (size_t)face * TOTAL;
    float acc[8];
#pragma unroll
    for (int k = 0; k < 8; k++) acc[k] = 0.f;

#pragma unroll
    for (int s = 0; s < 2; s++) {
        int l = s ? l1 : l0;
        float wl = s ? t : (1.f - t);
        int res = 512 >> l;
        float rf = (float)res;
        float x = fminf(fmaxf(u01 * rf - 0.5f, 0.f), rf - 1.f);
        float y = fminf(fmaxf(v01 * rf - 0.5f, 0.f), rf - 1.f);
        int x0 = (int)x, y0 = (int)y;
        int x1 = min(x0 + 1, res - 1), y1 = min(y0 + 1, res - 1);
        float fx = x - (float)x0, fy = y - (float)y0;
        size_t base = fb + d_offs[l];
        size_t r0 = (base + (size_t)y0 * res) * 4 + q;
        size_t r1 = (base + (size_t)y1 * res) * 4 + q;
        uint4 g00 = P4[r0 + (size_t)x0 * 4];
        uint4 g01 = P4[r0 + (size_t)x1 * 4];
        uint4 g10 = P4[r1 + (size_t)x0 * 4];
        uint4 g11 = P4[r1 + (size_t)x1 * 4];
        float w00 = wl * (1.f - fx) * (1.f - fy);
        float w01 = wl * fx * (1.f - fy);
        float w10 = wl * (1.f - fx) * fy;
        float w11 = wl * fx * fy;
        const unsigned* p00 = &g00.x; const unsigned* p01 = &g01.x;
        const unsigned* p10 = &g10.x; const unsigned* p11 = &g11.x;
#pragma unroll
        for (int k = 0; k < 4; k++) {
            float2 f00 = __half22float2(*(const __half2*)&p00[k]);
            float2 f01 = __half22float2(*(const __half2*)&p01[k]);
            float2 f10 = __half22float2(*(const __half2*)&p10[k]);
            float2 f11 = __half22float2(*(const __half2*)&p11[k]);
            acc[2 * k]     += w00 * f00.x + w01 * f01.x + w10 * f10.x + w11 * f11.x;
            acc[2 * k + 1] += w00 * f00.y + w01 * f01.y + w10 * f10.y + w11 * f11.y;
        }
    }
    float4* o4 = (float4*)&out[(size_t)b * 32 + q * 8];
    o4[0] = make_float4(acc[0], acc[1], acc[2], acc[3]);
    o4[1] = make_float4(acc[4], acc[5], acc[6], acc[7]);
}

extern "C" void kernel_launch(void* const* d_in, const int* in_sizes, int n_in,
                              void* d_out, int out_size) {
    const float* feat = (const float*)d_in[0];
    const float* w    = (const float*)d_in[1];
    const float* r    = (const float*)d_in[2];
    float* out = (float*)d_out;
    int B = in_sizes[2];

    k_transpose_pool1<<<dim3(8, 256, 6), 256>>>(feat);

    // levels 2+3 from level-1 (Rin=256): lvl2 k=2 (R=128), lvl3 k=4 (R=64)
    {
        int split = 6 * 128 * 128 * 4;          // 393216
        int total = split + 6 * 64 * 64 * 4;    // 491520
        k_pool_pair<<<(total + 255) / 256, 256>>>(split, total,
            128, 2, 393216, 64, 4, 491520, 0, 256);
    }
    // levels 4+5 from level-3 (Rin=64): lvl4 k=2 (R=32), lvl5 k=4 (R=16)
    {
        int split = 6 * 32 * 32 * 4;            // 24576
        int total = split + 6 * 16 * 16 * 4;    // 30720
        k_pool_pair<<<(total + 255) / 256, 256>>>(split, total,
            32, 2, 516096, 16, 4, 522240, 491520, 64);
    }

    k_filter_all<<<2046, 256>>>();

    long nthreads = (long)B * 4;
    k_fetch<<<(unsigned)((nthreads + 255) / 256), 256>>>(w, r, out, B);
}

// round 4
// speedup vs baseline: 1.2443x; 1.2443x over previous
#include <cuda_runtime.h>
#include <cuda_fp16.h>

#define NC 32
#define NLEV 6
#define TOTAL 349440   // sum of res^2 over 6 levels

// Pool: [face][texel(level-major)][channel], HALF, 134 MB
__device__ __half POOLH[6ll * TOTAL * NC];
// Scratch: unfiltered pooled levels 1..5, channel-last HALF. 33.5 MB
__device__ __half SCRATCH[523776ll * NC];

__constant__ int d_offs[NLEV] = {0, 262144, 327680, 344064, 348160, 349184};

// Fused-filter per-level tables (levels 1..5), 16x16 tiles
__constant__ int   F_start[5]  = {0, 1536, 1920, 2016, 2040};   // total 2046 blocks
__constant__ int   F_inOff[5]  = {0, 393216, 491520, 516096, 522240};
__constant__ int   F_poolOff[5]= {262144, 327680, 344064, 348160, 349184};
__constant__ float F_a2[5]     = {0.00243101246f, 0.030233088f, 0.137822329f, 0.419904f, 0.96059601f}; // rough^4

// ---------------------------------------------------------------------------
// K1: transpose feature (C,6,512,512) -> pool level0 (half, channel-last)
//     AND compute level-1 avg-pool into SCRATCH (half)
// ---------------------------------------------------------------------------
__global__ void k_transpose_pool1(const float* __restrict__ feat) {
    int f = blockIdx.z;
    int x0 = blockIdx.x * 64;
    int y0 = blockIdx.y * 2;
    __shared__ float s[32 * 129];
    int tid = threadIdx.x;

    for (int i = tid; i < 32 * 32; i += 256) {
        int c = i >> 5, v = i & 31;
        int t0 = v * 4;
        int yy = y0 + (t0 >> 6), xx = x0 + (t0 & 63);
        float4 d = *(const float4*)&feat[(((size_t)c * 6 + f) * 512 + yy) * 512 + xx];
        s[c * 129 + t0 + 0] = d.x;
        s[c * 129 + t0 + 1] = d.y;
        s[c * 129 + t0 + 2] = d.z;
        s[c * 129 + t0 + 3] = d.w;
    }
    __syncthreads();

    uint4* P4 = (uint4*)POOLH;   // one uint4 = 8 half channels
    for (int i = tid; i < 512; i += 256) {
        int t = i >> 2, q = i & 3;
        int yy = y0 + (t >> 6), xx = x0 + (t & 63);
        const float* sp = &s[(8 * q) * 129 + t];
        __half2 h0 = __floats2half2_rn(sp[0],       sp[129]);
        __half2 h1 = __floats2half2_rn(sp[2 * 129], sp[3 * 129]);
        __half2 h2 = __floats2half2_rn(sp[4 * 129], sp[5 * 129]);
        __half2 h3 = __floats2half2_rn(sp[6 * 129], sp[7 * 129]);
        uint4 o;
        o.x = *(unsigned*)&h0; o.y = *(unsigned*)&h1;
        o.z = *(unsigned*)&h2; o.w = *(unsigned*)&h3;
        P4[((size_t)f * TOTAL + (size_t)yy * 512 + xx) * 4 + q] = o;
    }
    // level-1 pool (half scratch)
    for (int i = tid; i < 1024; i += 256) {
        int c = i & 31, to = i >> 5;
        int t00 = 2 * to, t10 = 64 + 2 * to;
        float v = 0.25f * (s[c * 129 + t00] + s[c * 129 + t00 + 1] +
                           s[c * 129 + t10] + s[c * 129 + t10 + 1]);
        SCRATCH[(((size_t)f * 65536 + (size_t)(y0 >> 1) * 256 + (x0 >> 1) + to) * 32) + c] =
            __float2half_rn(v);
    }
}

// ---------------------------------------------------------------------------
// Pool pair: two levels computed directly from one source level (kxk avg).
// ---------------------------------------------------------------------------
__global__ void k_pool_pair(int split, int total,
                            int Ra, int ka, size_t dstA,
                            int Rb, int kb, size_t dstB,
                            size_t srcOff, int Rin) {
    int idx = blockIdx.x * 256 + threadIdx.x;
    if (idx >= total) return;
    int Rout, k; size_t dst; int rel;
    if (idx < split) { Rout = Ra; k = ka; dst = dstA; rel = idx; }
    else             { Rout = Rb; k = kb; dst = dstB; rel = idx - split; }
    int q = rel & 3;
    int t = rel >> 2;
    int f = t / (Rout * Rout);
    int rem = t - f * Rout * Rout;
    int oy = rem / Rout, ox = rem % Rout;
    const uint4* S4 = (const uint4*)SCRATCH;
    size_t sb = (srcOff + ((size_t)f * Rin + oy * k) * Rin + ox * k) * 4 + q;
    float a[8];
#pragma unroll
    for (int i = 0; i < 8; i++) a[i] = 0.f;
    for (int dy = 0; dy < k; dy++)
        for (int dx = 0; dx < k; dx++) {
            uint4 hv = S4[sb + ((size_t)dy * Rin + dx) * 4];
            const unsigned* p = &hv.x;
#pragma unroll
            for (int j = 0; j < 4; j++) {
                float2 fv = __half22float2(*(const __half2*)&p[j]);
                a[2 * j] += fv.x; a[2 * j + 1] += fv.y;
            }
        }
    float sc = 1.f / (float)(k * k);
    __half2 h0 = __floats2half2_rn(a[0] * sc, a[1] * sc);
    __half2 h1 = __floats2half2_rn(a[2] * sc, a[3] * sc);
    __half2 h2 = __floats2half2_rn(a[4] * sc, a[5] * sc);
    __half2 h3 = __floats2half2_rn(a[6] * sc, a[7] * sc);
    uint4 o;
    o.x = *(unsigned*)&h0; o.y = *(unsigned*)&h1;
    o.z = *(unsigned*)&h2; o.w = *(unsigned*)&h3;
    ((uint4*)SCRATCH)[(dst + (size_t)t) * 4 + q] = o;
}

// ---------------------------------------------------------------------------
// Fused GGX filter, all levels, 16x16 tiles (20x20 halo, fp16 smem).
// Lane layout: thread = (texel, q) with q fastest -> conflict-free LDS.128.
// Weight math per tap: 3 FMA + min + fast div, via precomputed n3 table.
// Accumulate unnormalized, scale by 1/wsum at the end.
// ---------------------------------------------------------------------------
__global__ void __launch_bounds__(256) k_filter_all() {
    int bid = blockIdx.x;
    int li = 0;
#pragma unroll
    for (int k = 1; k < 5; k++) if (bid >= F_start[k]) li = k;
    int R = 256 >> li;
    int nb = R >> 4;
    int rel = bid - F_start[li];
    int f  = rel / (nb * nb);
    int r2 = rel - f * nb * nb;
    int y0 = (r2 / nb) * 16, x0 = (r2 % nb) * 16;
    size_t inOff   = (size_t)F_inOff[li];
    size_t poolOff = (size_t)F_poolOff[li];
    float a2 = F_a2[li];
    float a2m1 = a2 - 1.f;
    float a2pi = a2 * 0.318309886183790672f;   // a2 / pi

    __shared__ uint4  hs[20 * 20 * 4];   // 25.6 KB halo data
    __shared__ float4 n3[20 * 20];       // 6.4 KB: (rn, uu*rn, vv*rn, 0)
    int tid = threadIdx.x;
    const uint4* S4 = (const uint4*)SCRATCH;
    float invR2 = 2.0f / (float)R;

    for (int i = tid; i < 1600; i += 256) {
        int t = i >> 2, q = i & 3;
        int hy = t / 20, hx = t - hy * 20;
        int gy = min(max(y0 - 2 + hy, 0), R - 1);
        int gx = min(max(x0 - 2 + hx, 0), R - 1);
        hs[i] = S4[(inOff + ((size_t)f * R + gy) * R + gx) * 4 + q];
    }
    for (int i = tid; i < 400; i += 256) {
        int hy = i / 20, hx = i - hy * 20;
        int gy = min(max(y0 - 2 + hy, 0), R - 1);
        int gx = min(max(x0 - 2 + hx, 0), R - 1);
        float uu = (gx + 0.5f) * invR2 - 1.f;
        float vv = (gy + 0.5f) * invR2 - 1.f;
        float rn = rsqrtf(1.f + uu * uu + vv * vv);
        n3[i] = make_float4(rn, uu * rn, vv * rn, 0.f);
    }
    __syncthreads();

    int q  = tid & 3;
    int tt = tid >> 2;
    uint4* P4 = (uint4*)POOLH;

#pragma unroll
    for (int p = 0; p < 4; p++) {
        int t  = p * 64 + tt;
        int ty = t >> 4, tx = t & 15;
        int gy = y0 + ty, gx = x0 + tx;
        float u = (gx + 0.5f) * invR2 - 1.f;
        float v = (gy + 0.5f) * invR2 - 1.f;
        float rn0 = rsqrtf(1.f + u * u + v * v);

        float wsum = 0.f;
        float acc[8];
#pragma unroll
        for (int i = 0; i < 8; i++) acc[i] = 0.f;

#pragma unroll
        for (int n = 0; n < 25; n++) {
            int di = n / 5, dj = n - (n / 5) * 5;
            int h = (ty + di) * 20 + (tx + dj);
            float4 nn = n3[h];
            float cs = (nn.x + u * nn.y + v * nn.z) * rn0;
            cs = fminf(cs, 1.f);
            float wg = 0.f;
            if (cs > 0.f) {
                float dn = cs * cs * a2m1 + 1.f;
                wg = __fdividef(a2pi, dn * dn);
            }
            wsum += wg;
            uint4 hv = hs[h * 4 + q];
            const unsigned* pp = &hv.x;
#pragma unroll
            for (int j = 0; j < 4; j++) {
                float2 fv = __half22float2(*(const __half2*)&pp[j]);
                acc[2 * j]     += wg * fv.x;
                acc[2 * j + 1] += wg * fv.y;
            }
        }
        float ws = 1.f / fmaxf(wsum, 1e-8f);
        __half2 h0 = __floats2half2_rn(acc[0] * ws, acc[1] * ws);
        __half2 h1 = __floats2half2_rn(acc[2] * ws, acc[3] * ws);
        __half2 h2 = __floats2half2_rn(acc[4] * ws, acc[5] * ws);
        __half2 h3 = __floats2half2_rn(acc[6] * ws, acc[7] * ws);
        uint4 o;
        o.x = *(unsigned*)&h0; o.y = *(unsigned*)&h1;
        o.z = *(unsigned*)&h2; o.w = *(unsigned*)&h3;
        P4[((size_t)f * TOTAL + poolOff + (size_t)gy * R + gx) * 4 + q] = o;
    }
}

// ---------------------------------------------------------------------------
// Fetch: 4 lanes per query, one uint4 (8 half channels) per lane per tap.
// ---------------------------------------------------------------------------
__global__ void k_fetch(const float* __restrict__ w, const float* __restrict__ rr,
                        float* __restrict__ out, int B) {
    long g = (long)blockIdx.x * 256 + threadIdx.x;
    if (g >= (long)B * 4) return;
    int b = (int)(g >> 2), q = (int)(g & 3);

    float dx = w[b * 3 + 0] * 2.f - 1.f;
    float dy = w[b * 3 + 1] * 2.f - 1.f;
    float dz = w[b * 3 + 2] * 2.f - 1.f;
    float ax = fabsf(dx), ay = fabsf(dy), az = fabsf(dz);
    bool cx = (ax >= ay) && (ax >= az);
    bool cy = (ay >= az) && !cx;
    float ma = cx ? ax : (cy ? ay : az);
    int face = cx ? (dx > 0.f ? 0 : 1) : (cy ? (dy > 0.f ? 2 : 3) : (dz > 0.f ? 4 : 5));
    float un = cx ? (dx > 0.f ? -dz : dz) : (cy ? dx : (dz > 0.f ? dx : -dx));
    float vn = cx ? -dy : (cy ? (dy > 0.f ? dz : -dz) : -dy);
    float inv = 1.f / ma;
    float u01 = (un * inv + 1.f) * 0.5f;
    float v01 = (vn * inv + 1.f) * 0.5f;

    float lev = fminf(fmaxf((rr[b] - 0.03f) * (1.f / 0.96f), 0.f), 1.f) * 5.f;
    int l0 = (int)lev;
    if (l0 > 5) l0 = 5;
    float t = lev - (float)l0;
    int l1 = min(l0 + 1, 5);

    const uint4* P4 = (const uint4*)POOLH;
    size_t fb = (size_t)face * TOTAL;
    float acc[8];
#pragma unroll
    for (int k = 0; k < 8; k++) acc[k] = 0.f;

#pragma unroll
    for (int s = 0; s < 2; s++) {
        int l = s ? l1 : l0;
        float wl = s ? t : (1.f - t);
        int res = 512 >> l;
        float rf = (float)res;
        float x = fminf(fmaxf(u01 * rf - 0.5f, 0.f), rf - 1.f);
        float y = fminf(fmaxf(v01 * rf - 0.5f, 0.f), rf - 1.f);
        int x0 = (int)x, y0 = (int)y;
        int x1 = min(x0 + 1, res - 1), y1 = min(y0 + 1, res - 1);
        float fx = x - (float)x0, fy = y - (float)y0;
        size_t base = fb + d_offs[l];
        size_t r0 = (base + (size_t)y0 * res) * 4 + q;
        size_t r1 = (base + (size_t)y1 * res) * 4 + q;
        uint4 g00 = P4[r0 + (size_t)x0 * 4];
        uint4 g01 = P4[r0 + (size_t)x1 * 4];
        uint4 g10 = P4[r1 + (size_t)x0 * 4];
        uint4 g11 = P4[r1 + (size_t)x1 * 4];
        float w00 = wl * (1.f - fx) * (1.f - fy);
        float w01 = wl * fx * (1.f - fy);
        float w10 = wl * (1.f - fx) * fy;
        float w11 = wl * fx * fy;
        const unsigned* p00 = &g00.x; const unsigned* p01 = &g01.x;
        const unsigned* p10 = &g10.x; const unsigned* p11 = &g11.x;
#pragma unroll
        for (int k = 0; k < 4; k++) {
            float2 f00 = __half22float2(*(const __half2*)&p00[k]);
            float2 f01 = __half22float2(*(const __half2*)&p01[k]);
            float2 f10 = __half22float2(*(const __half2*)&p10[k]);
            float2 f11 = __half22float2(*(const __half2*)&p11[k]);
            acc[2 * k]     += w00 * f00.x + w01 * f01.x + w10 * f10.x + w11 * f11.x;
            acc[2 * k + 1] += w00 * f00.y + w01 * f01.y + w10 * f10.y + w11 * f11.y;
        }
    }
    float4* o4 = (float4*)&out[(size_t)b * 32 + q * 8];
    o4[0] = make_float4(acc[0], acc[1], acc[2], acc[3]);
    o4[1] = make_float4(acc[4], acc[5], acc[6], acc[7]);
}

extern "C" void kernel_launch(void* const* d_in, const int* in_sizes, int n_in,
                              void* d_out, int out_size) {
    const float* feat = (const float*)d_in[0];
    const float* w    = (const float*)d_in[1];
    const float* r    = (const float*)d_in[2];
    float* out = (float*)d_out;
    int B = in_sizes[2];

    k_transpose_pool1<<<dim3(8, 256, 6), 256>>>(feat);

    // levels 2+3 from level-1 (Rin=256): lvl2 k=2 (R=128), lvl3 k=4 (R=64)
    {
        int split = 6 * 128 * 128 * 4;          // 393216
        int total = split + 6 * 64 * 64 * 4;    // 491520
        k_pool_pair<<<(total + 255) / 256, 256>>>(split, total,
            128, 2, 393216, 64, 4, 491520, 0, 256);
    }
    // levels 4+5 from level-3 (Rin=64): lvl4 k=2 (R=32), lvl5 k=4 (R=16)
    {
        int split = 6 * 32 * 32 * 4;            // 24576
        int total = split + 6 * 16 * 16 * 4;    // 30720
        k_pool_pair<<<(total + 255) / 256, 256>>>(split, total,
            32, 2, 516096, 16, 4, 522240, 491520, 64);
    }

    k_filter_all<<<2046, 256>>>();

    long nthreads = (long)B * 4;
    k_fetch<<<(unsigned)((nthreads + 255) / 256), 256>>>(w, r, out, B);
}

// round 5
// speedup vs baseline: 1.3013x; 1.0458x over previous
#include <cuda_runtime.h>
#include <cuda_fp16.h>

#define NC 32
#define NLEV 6
#define TOTAL 349440   // sum of res^2 over 6 levels

// Pool: [face][texel(level-major)][channel], HALF, 134 MB
__device__ __half POOLH[6ll * TOTAL * NC];
// Scratch: unfiltered pooled levels 1..5, channel-last HALF. 33.5 MB
__device__ __half SCRATCH[523776ll * NC];

__constant__ int d_offs[NLEV] = {0, 262144, 327680, 344064, 348160, 349184};

// Fused-filter per-level tables (levels 1..5), 16x16 tiles
__constant__ int   F_start[5]  = {0, 1536, 1920, 2016, 2040};   // total 2046 blocks
__constant__ int   F_inOff[5]  = {0, 393216, 491520, 516096, 522240};
__constant__ int   F_poolOff[5]= {262144, 327680, 344064, 348160, 349184};
__constant__ float F_a2[5]     = {0.00243101246f, 0.030233088f, 0.137822329f, 0.419904f, 0.96059601f}; // rough^4

// ---------------------------------------------------------------------------
// K1: transpose feature (C,6,512,512) -> pool level0 (half, channel-last)
//     AND compute level-1 avg-pool into SCRATCH (half)
// ---------------------------------------------------------------------------
__global__ void k_transpose_pool1(const float* __restrict__ feat) {
    int f = blockIdx.z;
    int x0 = blockIdx.x * 64;
    int y0 = blockIdx.y * 2;
    __shared__ float s[32 * 129];
    int tid = threadIdx.x;

    for (int i = tid; i < 32 * 32; i += 256) {
        int c = i >> 5, v = i & 31;
        int t0 = v * 4;
        int yy = y0 + (t0 >> 6), xx = x0 + (t0 & 63);
        float4 d = *(const float4*)&feat[(((size_t)c * 6 + f) * 512 + yy) * 512 + xx];
        s[c * 129 + t0 + 0] = d.x;
        s[c * 129 + t0 + 1] = d.y;
        s[c * 129 + t0 + 2] = d.z;
        s[c * 129 + t0 + 3] = d.w;
    }
    __syncthreads();

    uint4* P4 = (uint4*)POOLH;   // one uint4 = 8 half channels
    for (int i = tid; i < 512; i += 256) {
        int t = i >> 2, q = i & 3;
        int yy = y0 + (t >> 6), xx = x0 + (t & 63);
        const float* sp = &s[(8 * q) * 129 + t];
        __half2 h0 = __floats2half2_rn(sp[0],       sp[129]);
        __half2 h1 = __floats2half2_rn(sp[2 * 129], sp[3 * 129]);
        __half2 h2 = __floats2half2_rn(sp[4 * 129], sp[5 * 129]);
        __half2 h3 = __floats2half2_rn(sp[6 * 129], sp[7 * 129]);
        uint4 o;
        o.x = *(unsigned*)&h0; o.y = *(unsigned*)&h1;
        o.z = *(unsigned*)&h2; o.w = *(unsigned*)&h3;
        P4[((size_t)f * TOTAL + (size_t)yy * 512 + xx) * 4 + q] = o;
    }
    // level-1 pool (half scratch)
    for (int i = tid; i < 1024; i += 256) {
        int c = i & 31, to = i >> 5;
        int t00 = 2 * to, t10 = 64 + 2 * to;
        float v = 0.25f * (s[c * 129 + t00] + s[c * 129 + t00 + 1] +
                           s[c * 129 + t10] + s[c * 129 + t10 + 1]);
        SCRATCH[(((size_t)f * 65536 + (size_t)(y0 >> 1) * 256 + (x0 >> 1) + to) * 32) + c] =
            __float2half_rn(v);
    }
}

// ---------------------------------------------------------------------------
// All pools (levels 2..5) directly from level-1 (KxK box average).
// Segment boundaries are exact multiples of 256 -> no intra-block divergence.
// ---------------------------------------------------------------------------
template<int K>
__device__ __forceinline__ void pool_item(int rel, int Rout, int dst) {
    int q = rel & 3;
    int t = rel >> 2;
    int f = t / (Rout * Rout);
    int rem = t - f * Rout * Rout;
    int oy = rem / Rout, ox = rem % Rout;
    const uint4* S4 = (const uint4*)SCRATCH;
    size_t sb = (((size_t)f * 256 + oy * K) * 256 + ox * K) * 4 + q;
    float a[8];
#pragma unroll
    for (int i = 0; i < 8; i++) a[i] = 0.f;
    for (int dy = 0; dy < K; dy++) {
#pragma unroll
        for (int dx = 0; dx < K; dx++) {
            uint4 hv = S4[sb + ((size_t)dy * 256 + dx) * 4];
            const unsigned* p = &hv.x;
#pragma unroll
            for (int j = 0; j < 4; j++) {
                float2 fv = __half22float2(*(const __half2*)&p[j]);
                a[2 * j] += fv.x; a[2 * j + 1] += fv.y;
            }
        }
    }
    float sc = 1.f / (float)(K * K);
    __half2 h0 = __floats2half2_rn(a[0] * sc, a[1] * sc);
    __half2 h1 = __floats2half2_rn(a[2] * sc, a[3] * sc);
    __half2 h2 = __floats2half2_rn(a[4] * sc, a[5] * sc);
    __half2 h3 = __floats2half2_rn(a[6] * sc, a[7] * sc);
    uint4 o;
    o.x = *(unsigned*)&h0; o.y = *(unsigned*)&h1;
    o.z = *(unsigned*)&h2; o.w = *(unsigned*)&h3;
    ((uint4*)SCRATCH)[((size_t)dst + t) * 4 + q] = o;
}

__global__ void k_pool_all() {
    int idx = blockIdx.x * 256 + threadIdx.x;
    // heavy small segments first (early start)
    if (idx < 6144)        pool_item<16>(idx,          16, 522240);
    else if (idx < 30720)  pool_item<8> (idx - 6144,   32, 516096);
    else if (idx < 129024) pool_item<4> (idx - 30720,  64, 491520);
    else                   pool_item<2> (idx - 129024, 128, 393216);
}

// ---------------------------------------------------------------------------
// Fused GGX filter, all levels, 16x16 tiles (20x20 halo, fp16 smem).
// Lane layout: thread = (texel, q), q fastest -> conflict-free LDS.128.
// Weights deduped across the 4 q-lanes via shfl (width=4); a2/pi factor and
// cs>0 predicate removed (cancel in normalization / provably always true).
// ---------------------------------------------------------------------------
__global__ void __launch_bounds__(256) k_filter_all() {
    int bid = blockIdx.x;
    int li = 0;
#pragma unroll
    for (int k = 1; k < 5; k++) if (bid >= F_start[k]) li = k;
    int R = 256 >> li;
    int nb = R >> 4;
    int rel = bid - F_start[li];
    int f  = rel / (nb * nb);
    int r2 = rel - f * nb * nb;
    int y0 = (r2 / nb) * 16, x0 = (r2 % nb) * 16;
    size_t inOff   = (size_t)F_inOff[li];
    size_t poolOff = (size_t)F_poolOff[li];
    float a2m1 = F_a2[li] - 1.f;

    __shared__ uint4  hs[20 * 20 * 4];   // 25.6 KB halo data
    __shared__ float4 n3[20 * 20];       // 6.4 KB: (rn, uu*rn, vv*rn, 0)
    int tid = threadIdx.x;
    const uint4* S4 = (const uint4*)SCRATCH;
    float invR2 = 2.0f / (float)R;

    for (int i = tid; i < 1600; i += 256) {
        int t = i >> 2, q = i & 3;
        int hy = t / 20, hx = t - hy * 20;
        int gy = min(max(y0 - 2 + hy, 0), R - 1);
        int gx = min(max(x0 - 2 + hx, 0), R - 1);
        hs[i] = S4[(inOff + ((size_t)f * R + gy) * R + gx) * 4 + q];
    }
    for (int i = tid; i < 400; i += 256) {
        int hy = i / 20, hx = i - hy * 20;
        int gy = min(max(y0 - 2 + hy, 0), R - 1);
        int gx = min(max(x0 - 2 + hx, 0), R - 1);
        float uu = (gx + 0.5f) * invR2 - 1.f;
        float vv = (gy + 0.5f) * invR2 - 1.f;
        float rn = rsqrtf(1.f + uu * uu + vv * vv);
        n3[i] = make_float4(rn, uu * rn, vv * rn, 0.f);
    }
    __syncthreads();

    int q  = tid & 3;
    int tt = tid >> 2;
    uint4* P4 = (uint4*)POOLH;

#pragma unroll
    for (int p = 0; p < 4; p++) {
        int t  = p * 64 + tt;
        int ty = t >> 4, tx = t & 15;
        int gy = y0 + ty, gx = x0 + tx;
        float u = (gx + 0.5f) * invR2 - 1.f;
        float v = (gy + 0.5f) * invR2 - 1.f;
        float rn0 = rsqrtf(1.f + u * u + v * v);

        // lane q computes weights for taps n = 4k+q
        float wl[7];
        float wsum = 0.f;
#pragma unroll
        for (int k = 0; k < 7; k++) {
            int n = 4 * k + q;
            float wg = 0.f;
            if (n < 25) {
                int di = n / 5, dj = n - (n / 5) * 5;
                float4 nn = n3[(ty + di) * 20 + (tx + dj)];
                float cs = fminf((nn.x + u * nn.y + v * nn.z) * rn0, 1.f);
                float dn = fmaf(cs * cs, a2m1, 1.f);
                wg = __fdividef(1.f, dn * dn);
            }
            wl[k] = wg;
            wsum += wg;
        }
        // sum over the 4-lane group
        wsum += __shfl_xor_sync(0xffffffffu, wsum, 1, 4);
        wsum += __shfl_xor_sync(0xffffffffu, wsum, 2, 4);

        float acc[8];
#pragma unroll
        for (int i = 0; i < 8; i++) acc[i] = 0.f;

#pragma unroll
        for (int n = 0; n < 25; n++) {
            float wg = __shfl_sync(0xffffffffu, wl[n >> 2], n & 3, 4);
            int h = (ty + n / 5) * 20 + (tx + n - (n / 5) * 5);
            uint4 hv = hs[h * 4 + q];
            const unsigned* pp = &hv.x;
#pragma unroll
            for (int j = 0; j < 4; j++) {
                float2 fv = __half22float2(*(const __half2*)&pp[j]);
                acc[2 * j]     += wg * fv.x;
                acc[2 * j + 1] += wg * fv.y;
            }
        }
        float ws = __fdividef(1.f, fmaxf(wsum, 1e-8f));
        __half2 h0 = __floats2half2_rn(acc[0] * ws, acc[1] * ws);
        __half2 h1 = __floats2half2_rn(acc[2] * ws, acc[3] * ws);
        __half2 h2 = __floats2half2_rn(acc[4] * ws, acc[5] * ws);
        __half2 h3 = __floats2half2_rn(acc[6] * ws, acc[7] * ws);
        uint4 o;
        o.x = *(unsigned*)&h0; o.y = *(unsigned*)&h1;
        o.z = *(unsigned*)&h2; o.w = *(unsigned*)&h3;
        P4[((size_t)f * TOTAL + poolOff + (size_t)gy * R + gx) * 4 + q] = o;
    }
}

// ---------------------------------------------------------------------------
// Fetch: 4 lanes per query, one uint4 (8 half channels) per lane per tap.
// ---------------------------------------------------------------------------
__global__ void k_fetch(const float* __restrict__ w, const float* __restrict__ rr,
                        float* __restrict__ out, int B) {
    long g = (long)blockIdx.x * 256 + threadIdx.x;
    if (g >= (long)B * 4) return;
    int b = (int)(g >> 2), q = (int)(g & 3);

    float dx = w[b * 3 + 0] * 2.f - 1.f;
    float dy = w[b * 3 + 1] * 2.f - 1.f;
    float dz = w[b * 3 + 2] * 2.f - 1.f;
    float ax = fabsf(dx), ay = fabsf(dy), az = fabsf(dz);
    bool cx = (ax >= ay) && (ax >= az);
    bool cy = (ay >= az) && !cx;
    float ma = cx ? ax : (cy ? ay : az);
    int face = cx ? (dx > 0.f ? 0 : 1) : (cy ? (dy > 0.f ? 2 : 3) : (dz > 0.f ? 4 : 5));
    float un = cx ? (dx > 0.f ? -dz : dz) : (cy ? dx : (dz > 0.f ? dx : -dx));
    float vn = cx ? -dy : (cy ? (dy > 0.f ? dz : -dz) : -dy);
    float inv = 1.f / ma;
    float u01 = (un * inv + 1.f) * 0.5f;
    float v01 = (vn * inv + 1.f) * 0.5f;

    float lev = fminf(fmaxf((rr[b] - 0.03f) * (1.f / 0.96f), 0.f), 1.f) * 5.f;
    int l0 = (int)lev;
    if (l0 > 5) l0 = 5;
    float t = lev - (float)l0;
    int l1 = min(l0 + 1, 5);

    const uint4* P4 = (const uint4*)POOLH;
    size_t fb = (size_t)face * TOTAL;
    float acc[8];
#pragma unroll
    for (int k = 0; k < 8; k++) acc[k] = 0.f;

#pragma unroll
    for (int s = 0; s < 2; s++) {
        int l = s ? l1 : l0;
        float wl = s ? t : (1.f - t);
        int res = 512 >> l;
        float rf = (float)res;
        float x = fminf(fmaxf(u01 * rf - 0.5f, 0.f), rf - 1.f);
        float y = fminf(fmaxf(v01 * rf - 0.5f, 0.f), rf - 1.f);
        int x0 = (int)x, y0 = (int)y;
        int x1 = min(x0 + 1, res - 1), y1 = min(y0 + 1, res - 1);
        float fx = x - (float)x0, fy = y - (float)y0;
        size_t base = fb + d_offs[l];
        size_t r0 = (base + (size_t)y0 * res) * 4 + q;
        size_t r1 = (base + (size_t)y1 * res) * 4 + q;
        uint4 g00 = P4[r0 + (size_t)x0 * 4];
        uint4 g01 = P4[r0 + (size_t)x1 * 4];
        uint4 g10 = P4[r1 + (size_t)x0 * 4];
        uint4 g11 = P4[r1 + (size_t)x1 * 4];
        float w00 = wl * (1.f - fx) * (1.f - fy);
        float w01 = wl * fx * (1.f - fy);
        float w10 = wl * (1.f - fx) * fy;
        float w11 = wl * fx * fy;
        const unsigned* p00 = &g00.x; const unsigned* p01 = &g01.x;
        const unsigned* p10 = &g10.x; const unsigned* p11 = &g11.x;
#pragma unroll
        for (int k = 0; k < 4; k++) {
            float2 f00 = __half22float2(*(const __half2*)&p00[k]);
            float2 f01 = __half22float2(*(const __half2*)&p01[k]);
            float2 f10 = __half22float2(*(const __half2*)&p10[k]);
            float2 f11 = __half22float2(*(const __half2*)&p11[k]);
            acc[2 * k]     += w00 * f00.x + w01 * f01.x + w10 * f10.x + w11 * f11.x;
            acc[2 * k + 1] += w00 * f00.y + w01 * f01.y + w10 * f10.y + w11 * f11.y;
        }
    }
    float4* o4 = (float4*)&out[(size_t)b * 32 + q * 8];
    o4[0] = make_float4(acc[0], acc[1], acc[2], acc[3]);
    o4[1] = make_float4(acc[4], acc[5], acc[6], acc[7]);
}

extern "C" void kernel_launch(void* const* d_in, const int* in_sizes, int n_in,
                              void* d_out, int out_size) {
    const float* feat = (const float*)d_in[0];
    const float* w    = (const float*)d_in[1];
    const float* r    = (const float*)d_in[2];
    float* out = (float*)d_out;
    int B = in_sizes[2];

    k_transpose_pool1<<<dim3(8, 256, 6), 256>>>(feat);
    k_pool_all<<<2040, 256>>>();
    k_filter_all<<<2046, 256>>>();

    long nthreads = (long)B * 4;
    k_fetch<<<(unsigned)((nthreads + 255) / 256), 256>>>(w, r, out, B);
}

// round 7
// speedup vs baseline: 1.3319x; 1.0235x over previous
#include <cuda_runtime.h>
#include <cuda_fp16.h>

#define NC 32
#define NLEV 6
#define TOTAL 349440   // sum of res^2 over 6 levels

// Pool: [face][texel(level-major)][channel], HALF, 134 MB
__device__ __half POOLH[6ll * TOTAL * NC];
// Scratch: unfiltered pooled levels 1..5, channel-last HALF. 33.5 MB
__device__ __half SCRATCH[523776ll * NC];

__constant__ int d_offs[NLEV] = {0, 262144, 327680, 344064, 348160, 349184};

// Fused-filter per-level tables (levels 1..5), 16x16 tiles
__constant__ int   F_start[5]  = {0, 1536, 1920, 2016, 2040};   // total 2046 blocks
__constant__ int   F_inOff[5]  = {0, 393216, 491520, 516096, 522240};
__constant__ int   F_poolOff[5]= {262144, 327680, 344064, 348160, 349184};
__constant__ float F_a2[5]     = {0.00243101246f, 0.030233088f, 0.137822329f, 0.419904f, 0.96059601f}; // rough^4

// ---------------------------------------------------------------------------
// K1: transpose feature (C,6,512,512) -> pool level0 (half, channel-last)
//     AND compute level-1 avg-pool into SCRATCH (half)
// ---------------------------------------------------------------------------
__global__ void k_transpose_pool1(const float* __restrict__ feat) {
    int f = blockIdx.z;
    int x0 = blockIdx.x * 64;
    int y0 = blockIdx.y * 2;
    __shared__ float s[32 * 129];
    int tid = threadIdx.x;

    for (int i = tid; i < 32 * 32; i += 256) {
        int c = i >> 5, v = i & 31;
        int t0 = v * 4;
        int yy = y0 + (t0 >> 6), xx = x0 + (t0 & 63);
        float4 d = *(const float4*)&feat[(((size_t)c * 6 + f) * 512 + yy) * 512 + xx];
        s[c * 129 + t0 + 0] = d.x;
        s[c * 129 + t0 + 1] = d.y;
        s[c * 129 + t0 + 2] = d.z;
        s[c * 129 + t0 + 3] = d.w;
    }
    __syncthreads();

    uint4* P4 = (uint4*)POOLH;   // one uint4 = 8 half channels
    for (int i = tid; i < 512; i += 256) {
        int t = i >> 2, q = i & 3;
        int yy = y0 + (t >> 6), xx = x0 + (t & 63);
        const float* sp = &s[(8 * q) * 129 + t];
        __half2 h0 = __floats2half2_rn(sp[0],       sp[129]);
        __half2 h1 = __floats2half2_rn(sp[2 * 129], sp[3 * 129]);
        __half2 h2 = __floats2half2_rn(sp[4 * 129], sp[5 * 129]);
        __half2 h3 = __floats2half2_rn(sp[6 * 129], sp[7 * 129]);
        uint4 o;
        o.x = *(unsigned*)&h0; o.y = *(unsigned*)&h1;
        o.z = *(unsigned*)&h2; o.w = *(unsigned*)&h3;
        P4[((size_t)f * TOTAL + (size_t)yy * 512 + xx) * 4 + q] = o;
    }
    // level-1 pool (half scratch)
    for (int i = tid; i < 1024; i += 256) {
        int c = i & 31, to = i >> 5;
        int t00 = 2 * to, t10 = 64 + 2 * to;
        float v = 0.25f * (s[c * 129 + t00] + s[c * 129 + t00 + 1] +
                           s[c * 129 + t10] + s[c * 129 + t10 + 1]);
        SCRATCH[(((size_t)f * 65536 + (size_t)(y0 >> 1) * 256 + (x0 >> 1) + to) * 32) + c] =
            __float2half_rn(v);
    }
}

// ---------------------------------------------------------------------------
// All pools (levels 2..5) directly from level-1 (KxK box average).
// ---------------------------------------------------------------------------
template<int K>
__device__ __forceinline__ void pool_item(int rel, int Rout, int dst) {
    int q = rel & 3;
    int t = rel >> 2;
    int f = t / (Rout * Rout);
    int rem = t - f * Rout * Rout;
    int oy = rem / Rout, ox = rem % Rout;
    const uint4* S4 = (const uint4*)SCRATCH;
    size_t sb = (((size_t)f * 256 + oy * K) * 256 + ox * K) * 4 + q;
    float a[8];
#pragma unroll
    for (int i = 0; i < 8; i++) a[i] = 0.f;
    for (int dy = 0; dy < K; dy++) {
#pragma unroll
        for (int dx = 0; dx < K; dx++) {
            uint4 hv = S4[sb + ((size_t)dy * 256 + dx) * 4];
            const unsigned* p = &hv.x;
#pragma unroll
            for (int j = 0; j < 4; j++) {
                float2 fv = __half22float2(*(const __half2*)&p[j]);
                a[2 * j] += fv.x; a[2 * j + 1] += fv.y;
            }
        }
    }
    float sc = 1.f / (float)(K * K);
    __half2 h0 = __floats2half2_rn(a[0] * sc, a[1] * sc);
    __half2 h1 = __floats2half2_rn(a[2] * sc, a[3] * sc);
    __half2 h2 = __floats2half2_rn(a[4] * sc, a[5] * sc);
    __half2 h3 = __floats2half2_rn(a[6] * sc, a[7] * sc);
    uint4 o;
    o.x = *(unsigned*)&h0; o.y = *(unsigned*)&h1;
    o.z = *(unsigned*)&h2; o.w = *(unsigned*)&h3;
    ((uint4*)SCRATCH)[((size_t)dst + t) * 4 + q] = o;
}

__global__ void k_pool_all() {
    int idx = blockIdx.x * 256 + threadIdx.x;
    if (idx < 6144)        pool_item<16>(idx,          16, 522240);
    else if (idx < 30720)  pool_item<8> (idx - 6144,   32, 516096);
    else if (idx < 129024) pool_item<4> (idx - 30720,  64, 491520);
    else                   pool_item<2> (idx - 129024, 128, 393216);
}

// ---------------------------------------------------------------------------
// Fused GGX filter, all levels, 16x16 tiles (20x20 halo, fp16 smem).
// Lane layout: thread = (texel, q), q fastest -> conflict-free LDS.128.
// Weights deduped across q-lanes via shfl, PRE-NORMALIZED (sum=1), and the
// channel math runs as HFMA2 in fp16 with fp32 flush every 5 taps.
// ---------------------------------------------------------------------------
__global__ void __launch_bounds__(256) k_filter_all() {
    int bid = blockIdx.x;
    int li = 0;
#pragma unroll
    for (int k = 1; k < 5; k++) if (bid >= F_start[k]) li = k;
    int R = 256 >> li;
    int nb = R >> 4;
    int rel = bid - F_start[li];
    int f  = rel / (nb * nb);
    int r2 = rel - f * nb * nb;
    int y0 = (r2 / nb) * 16, x0 = (r2 % nb) * 16;
    size_t inOff   = (size_t)F_inOff[li];
    size_t poolOff = (size_t)F_poolOff[li];
    float a2m1 = F_a2[li] - 1.f;

    __shared__ uint4  hs[20 * 20 * 4];   // 25.6 KB halo data
    __shared__ float4 n3[20 * 20];       // 6.4 KB: (rn, uu*rn, vv*rn, 0)
    int tid = threadIdx.x;
    const uint4* S4 = (const uint4*)SCRATCH;
    float invR2 = 2.0f / (float)R;

    for (int i = tid; i < 1600; i += 256) {
        int t = i >> 2, q = i & 3;
        int hy = t / 20, hx = t - hy * 20;
        int gy = min(max(y0 - 2 + hy, 0), R - 1);
        int gx = min(max(x0 - 2 + hx, 0), R - 1);
        hs[i] = S4[(inOff + ((size_t)f * R + gy) * R + gx) * 4 + q];
    }
    for (int i = tid; i < 400; i += 256) {
        int hy = i / 20, hx = i - hy * 20;
        int gy = min(max(y0 - 2 + hy, 0), R - 1);
        int gx = min(max(x0 - 2 + hx, 0), R - 1);
        float uu = (gx + 0.5f) * invR2 - 1.f;
        float vv = (gy + 0.5f) * invR2 - 1.f;
        float rn = rsqrtf(1.f + uu * uu + vv * vv);
        n3[i] = make_float4(rn, uu * rn, vv * rn, 0.f);
    }
    __syncthreads();

    int q  = tid & 3;
    int tt = tid >> 2;
    uint4* P4 = (uint4*)POOLH;

#pragma unroll
    for (int p = 0; p < 4; p++) {
        int t  = p * 64 + tt;
        int ty = t >> 4, tx = t & 15;
        int gy = y0 + ty, gx = x0 + tx;
        float u = (gx + 0.5f) * invR2 - 1.f;
        float v = (gy + 0.5f) * invR2 - 1.f;
        float rn0 = rsqrtf(1.f + u * u + v * v);

        // lane q computes weights for taps n = 4k+q
        float wl[7];
        float wsum = 0.f;
#pragma unroll
        for (int k = 0; k < 7; k++) {
            int n = 4 * k + q;
            float wg = 0.f;
            if (n < 25) {
                int di = n / 5, dj = n - (n / 5) * 5;
                float4 nn = n3[(ty + di) * 20 + (tx + dj)];
                float cs = fminf((nn.x + u * nn.y + v * nn.z) * rn0, 1.f);
                float dn = fmaf(cs * cs, a2m1, 1.f);
                wg = __fdividef(1.f, dn * dn);
            }
            wl[k] = wg;
            wsum += wg;
        }
        wsum += __shfl_xor_sync(0xffffffffu, wsum, 1, 4);
        wsum += __shfl_xor_sync(0xffffffffu, wsum, 2, 4);
        float ws = __fdividef(1.f, fmaxf(wsum, 1e-8f));
#pragma unroll
        for (int k = 0; k < 7; k++) wl[k] *= ws;   // pre-normalized weights

        float accf[8];
#pragma unroll
        for (int i = 0; i < 8; i++) accf[i] = 0.f;

        // 5 groups of 5 taps: fp16 HFMA2 accumulate, fp32 flush per group
#pragma unroll
        for (int g = 0; g < 5; g++) {
            __half2 a4[4];
            __half2 z = __float2half2_rn(0.f);
            a4[0] = z; a4[1] = z; a4[2] = z; a4[3] = z;
#pragma unroll
            for (int m = 0; m < 5; m++) {
                int n = g * 5 + m;
                float wg = __shfl_sync(0xffffffffu, wl[n >> 2], n & 3, 4);
                __half2 wh = __float2half2_rn(wg);
                int h = (ty + g) * 20 + (tx + m);
                uint4 hv = hs[h * 4 + q];
                const __half2* pp = (const __half2*)&hv;
                a4[0] = __hfma2(wh, pp[0], a4[0]);
                a4[1] = __hfma2(wh, pp[1], a4[1]);
                a4[2] = __hfma2(wh, pp[2], a4[2]);
                a4[3] = __hfma2(wh, pp[3], a4[3]);
            }
#pragma unroll
            for (int j = 0; j < 4; j++) {
                float2 fv = __half22float2(a4[j]);
                accf[2 * j]     += fv.x;
                accf[2 * j + 1] += fv.y;
            }
        }

        __half2 h0 = __floats2half2_rn(accf[0], accf[1]);
        __half2 h1 = __floats2half2_rn(accf[2], accf[3]);
        __half2 h2 = __floats2half2_rn(accf[4], accf[5]);
        __half2 h3 = __floats2half2_rn(accf[6], accf[7]);
        uint4 o;
        o.x = *(unsigned*)&h0; o.y = *(unsigned*)&h1;
        o.z = *(unsigned*)&h2; o.w = *(unsigned*)&h3;
        P4[((size_t)f * TOTAL + poolOff + (size_t)gy * R + gx) * 4 + q] = o;
    }
}

// ---------------------------------------------------------------------------
// Fetch: 4 lanes per query, one uint4 (8 half channels) per lane per tap.
// ---------------------------------------------------------------------------
__global__ void k_fetch(const float* __restrict__ w, const float* __restrict__ rr,
                        float* __restrict__ out, int B) {
    long g = (long)blockIdx.x * 256 + threadIdx.x;
    if (g >= (long)B * 4) return;
    int b = (int)(g >> 2), q = (int)(g & 3);

    float dx = w[b * 3 + 0] * 2.f - 1.f;
    float dy = w[b * 3 + 1] * 2.f - 1.f;
    float dz = w[b * 3 + 2] * 2.f - 1.f;
    float ax = fabsf(dx), ay = fabsf(dy), az = fabsf(dz);
    bool cx = (ax >= ay) && (ax >= az);
    bool cy = (ay >= az) && !cx;
    float ma = cx ? ax : (cy ? ay : az);
    int face = cx ? (dx > 0.f ? 0 : 1) : (cy ? (dy > 0.f ? 2 : 3) : (dz > 0.f ? 4 : 5));
    float un = cx ? (dx > 0.f ? -dz : dz) : (cy ? dx : (dz > 0.f ? dx : -dx));
    float vn = cx ? -dy : (cy ? (dy > 0.f ? dz : -dz) : -dy);
    float inv = 1.f / ma;
    float u01 = (un * inv + 1.f) * 0.5f;
    float v01 = (vn * inv + 1.f) * 0.5f;

    float lev = fminf(fmaxf((rr[b] - 0.03f) * (1.f / 0.96f), 0.f), 1.f) * 5.f;
    int l0 = (int)lev;
    if (l0 > 5) l0 = 5;
    float t = lev - (float)l0;
    int l1 = min(l0 + 1, 5);

    const uint4* P4 = (const uint4*)POOLH;
    size_t fb = (size_t)face * TOTAL;
    float acc[8];
#pragma unroll
    for (int k = 0; k < 8; k++) acc[k] = 0.f;

#pragma unroll
    for (int s = 0; s < 2; s++) {
        int l = s ? l1 : l0;
        float wl = s ? t : (1.f - t);
        int res = 512 >> l;
        float rf = (float)res;
        float x = fminf(fmaxf(u01 * rf - 0.5f, 0.f), rf - 1.f);
        float y = fminf(fmaxf(v01 * rf - 0.5f, 0.f), rf - 1.f);
        int x0 = (int)x, y0 = (int)y;
        int x1 = min(x0 + 1, res - 1), y1 = min(y0 + 1, res - 1);
        float fx = x - (float)x0, fy = y - (float)y0;
        size_t base = fb + d_offs[l];
        size_t r0 = (base + (size_t)y0 * res) * 4 + q;
        size_t r1 = (base + (size_t)y1 * res) * 4 + q;
        uint4 g00 = P4[r0 + (size_t)x0 * 4];
        uint4 g01 = P4[r0 + (size_t)x1 * 4];
        uint4 g10 = P4[r1 + (size_t)x0 * 4];
        uint4 g11 = P4[r1 + (size_t)x1 * 4];
        float w00 = wl * (1.f - fx) * (1.f - fy);
        float w01 = wl * fx * (1.f - fy);
        float w10 = wl * (1.f - fx) * fy;
        float w11 = wl * fx * fy;
        const unsigned* p00 = &g00.x; const unsigned* p01 = &g01.x;
        const unsigned* p10 = &g10.x; const unsigned* p11 = &g11.x;
#pragma unroll
        for (int k = 0; k < 4; k++) {
            float2 f00 = __half22float2(*(const __half2*)&p00[k]);
            float2 f01 = __half22float2(*(const __half2*)&p01[k]);
            float2 f10 = __half22float2(*(const __half2*)&p10[k]);
            float2 f11 = __half22float2(*(const __half2*)&p11[k]);
            acc[2 * k]     += w00 * f00.x + w01 * f01.x + w10 * f10.x + w11 * f11.x;
            acc[2 * k + 1] += w00 * f00.y + w01 * f01.y + w10 * f10.y + w11 * f11.y;
        }
    }
    float4* o4 = (float4*)&out[(size_t)b * 32 + q * 8];
    o4[0] = make_float4(acc[0], acc[1], acc[2], acc[3]);
    o4[1] = make_float4(acc[4], acc[5], acc[6], acc[7]);
}

extern "C" void kernel_launch(void* const* d_in, const int* in_sizes, int n_in,
                              void* d_out, int out_size) {
    const float* feat = (const float*)d_in[0];
    const float* w    = (const float*)d_in[1];
    const float* r    = (const float*)d_in[2];
    float* out = (float*)d_out;
    int B = in_sizes[2];

    k_transpose_pool1<<<dim3(8, 256, 6), 256>>>(feat);
    k_pool_all<<<2040, 256>>>();
    k_filter_all<<<2046, 256>>>();

    long nthreads = (long)B * 4;
    k_fetch<<<(unsigned)((nthreads + 255) / 256), 256>>>(w, r, out, B);
}